// round 12
// baseline (speedup 1.0000x reference)
#include <cuda_runtime.h>
#include <cuda_bf16.h>
#include <math.h>
#include <stdint.h>

typedef __nv_bfloat16 bf16;
typedef long long ll;

// Problem constants
#define PB 4
#define PS 1024
#define PT 1024
#define PD 512
#define PH 8
#define PHD (PH * PD)      // 4096
#define PBS (PB * PS)      // 4096
#define LN_EPS 1e-5f

#define DDc ((ll)PD * PD)     // 262144
#define SDc ((ll)PS * PD)     // 524288
#define STc ((ll)PS * PT)     // 1048576

// ---------------------------------------------------------------------------
// Scratch (device globals; no allocation allowed)
// ---------------------------------------------------------------------------
__device__ float g_V  [PB * PH * PS * PD];
__device__ float g_SC [PB * PH * PS * PT];
__device__ float g_ATT[PBS * PD];
__device__ float g_X1 [PBS * PD];
__device__ float g_X2 [PBS * PD];
__device__ float g_WB [PHD * PD];
__device__ float g_BT0[PD];
__device__ float g_BT1[PD];

// hi/lo bf16 operand buffers
__device__ bf16 g_xb_h [PBS * PD],  g_xb_l [PBS * PD];
__device__ bf16 g_encb_h[PBS * PD], g_encb_l[PBS * PD];
__device__ bf16 g_wob_h[PH * PD * PD], g_wob_l[PH * PD * PD];
__device__ bf16 g_Qb_h[PB * PH * PS * PD], g_Qb_l[PB * PH * PS * PD];
__device__ bf16 g_Kb_h[PB * PH * PS * PD], g_Kb_l[PB * PH * PS * PD];
__device__ bf16 g_SCb_h[PB * PH * PS * PT], g_SCb_l[PB * PH * PS * PT];
__device__ bf16 g_CATb_h[PBS * PHD], g_CATb_l[PBS * PHD];
__device__ bf16 g_FFHb_h[PBS * 2048], g_FFHb_l[PBS * 2048];
__device__ bf16 g_X1b_h[PBS * PD], g_X1b_l[PBS * PD];
__device__ bf16 g_X2b_h[PBS * PD], g_X2b_l[PBS * PD];

// transposed weights hi/lo
__device__ bf16 g_twq_h[PH * PD * PD], g_twq_l[PH * PD * PD];
__device__ bf16 g_twk_h[PH * PD * PD], g_twk_l[PH * PD * PD];
__device__ bf16 g_twv_h[PH * PD * PD], g_twv_l[PH * PD * PD];
__device__ bf16 g_twf_h[PD * PHD],    g_twf_l[PD * PHD];
__device__ bf16 g_WBT0_h[PD * PHD],   g_WBT0_l[PD * PHD];
__device__ bf16 g_WBT1_h[PD * PHD],   g_WBT1_l[PD * PHD];
__device__ bf16 g_tv_h[PB * PH * PT * PD], g_tv_l[PB * PH * PT * PD];
__device__ bf16 g_tf1_h[2048 * PD],   g_tf1_l[2048 * PD];
__device__ bf16 g_tf2_h[PD * 2048],   g_tf2_l[PD * 2048];

// ---------------------------------------------------------------------------
// Helpers (family-common PTX only: cp.async + ldmatrix + mma.sync)
// ---------------------------------------------------------------------------
__device__ __forceinline__ uint32_t smem_u32(const void* p) {
    uint32_t a;
    asm("{ .reg .u64 t; cvta.to.shared.u64 t, %1; cvt.u32.u64 %0, t; }"
        : "=r"(a) : "l"(p));
    return a;
}
__device__ __forceinline__ void ldsm4(uint32_t* r, uint32_t addr) {
    asm volatile("ldmatrix.sync.aligned.m8n8.x4.shared.b16 {%0,%1,%2,%3}, [%4];"
                 : "=r"(r[0]), "=r"(r[1]), "=r"(r[2]), "=r"(r[3]) : "r"(addr));
}
__device__ __forceinline__ void mma_bf16(float* c, const uint32_t* a,
                                         uint32_t b0, uint32_t b1) {
    asm volatile(
        "mma.sync.aligned.m16n8k16.row.col.f32.bf16.bf16.f32 "
        "{%0,%1,%2,%3}, {%4,%5,%6,%7}, {%8,%9}, {%0,%1,%2,%3};"
        : "+f"(c[0]), "+f"(c[1]), "+f"(c[2]), "+f"(c[3])
        : "r"(a[0]), "r"(a[1]), "r"(a[2]), "r"(a[3]), "r"(b0), "r"(b1));
}
__device__ __forceinline__ void cpa16(uint32_t d, const void* s) {
    asm volatile("cp.async.cg.shared.global [%0], [%1], 16;" :: "r"(d), "l"(s) : "memory");
}
__device__ __forceinline__ void cpa_commit() {
    asm volatile("cp.async.commit_group;" ::: "memory");
}
template <int N> __device__ __forceinline__ void cpa_wait() {
    asm volatile("cp.async.wait_group %0;" :: "n"(N) : "memory");
}
__device__ __forceinline__ uint32_t bpack(bf16 a, bf16 b) {
    __nv_bfloat162 t = __halves2bfloat162(a, b);
    return *reinterpret_cast<uint32_t*>(&t);
}
// write hi/lo pair for two consecutive elements
__device__ __forceinline__ void hl_store2(bf16* Ch, bf16* Cl, ll off, float a, float b) {
    bf16 ha = __float2bfloat16(a), hb = __float2bfloat16(b);
    *(uint32_t*)(Ch + off) = bpack(ha, hb);
    *(uint32_t*)(Cl + off) = bpack(__float2bfloat16(a - __bfloat162float(ha)),
                                   __float2bfloat16(b - __bfloat162float(hb)));
}

// ---------------------------------------------------------------------------
// HMMA bf16x3 GEMM, all-bf16 operands: C[z] = alpha * (Ah+Al) @ (Bh+Bl)^T + bias
// A: bf16 hi/lo [M,K]; B: bf16 hi/lo [N,K]. Tile 128x128, K-chunk 32.
// cp.async double-buffered, 8 warps (4x2), warp tile 32x64, fp32 accum.
// SMEM per stage: 4 regions (Ah,Al,Bh,Bl) of 128 rows x 80B pitch = 40960B.
// EPI 0: fp32 C. EPI 1: hi/lo bf16 C.
// ---------------------------------------------------------------------------
#define PITCH 80
#define REGION 10240            // 128 * 80
#define STAGE_B 40960           // 4 * REGION
#define SMEM_DYN (2 * STAGE_B)  // 81920

template <int EPI, bool RELU>
__global__ __launch_bounds__(256, 2)
void mmb_kernel(const bf16* __restrict__ Ah, const bf16* __restrict__ Al,
                const bf16* __restrict__ Bh, const bf16* __restrict__ Bl,
                const float* __restrict__ bias,
                float* __restrict__ Cf, bf16* __restrict__ Ch, bf16* __restrict__ Cl,
                int K, int lda, int ldb, int ldc, int zdiv,
                ll aOut, ll aIn, ll bOut, ll bIn, ll cOut, ll cIn, ll biasIn,
                float alpha)
{
    extern __shared__ char sm[];

    const int tid = threadIdx.x;
    const int wid = tid >> 5;
    const int lane = tid & 31;

    const int z = blockIdx.z;
    const int zo = z / zdiv, zi = z % zdiv;
    Ah += zo * aOut + zi * aIn;  Al += zo * aOut + zi * aIn;
    Bh += zo * bOut + zi * bIn;  Bl += zo * bOut + zi * bIn;
    const ll cOff = zo * cOut + zi * cIn;
    if (EPI == 0) Cf += cOff; else { Ch += cOff; Cl += cOff; }
    const float* biasP = bias ? (bias + zi * biasIn) : nullptr;

    const uint32_t su = smem_u32(sm);
    const int bm = blockIdx.y * 128;
    const int bn = blockIdx.x * 128;
    const int wm = (wid >> 1) * 32;
    const int wn = (wid & 1) * 64;
    const int nc = K >> 5;

    // cp.async mapping: thread -> (row = tid>>1, two 16B segs c0,c0+1)
    const int grow = tid >> 1;
    const int gc0  = (tid & 1) * 2;
    const bf16* gAh = Ah + (ll)(bm + grow) * lda + gc0 * 8;
    const bf16* gAl = Al + (ll)(bm + grow) * lda + gc0 * 8;
    const bf16* gBh = Bh + (ll)(bn + grow) * ldb + gc0 * 8;
    const bf16* gBl = Bl + (ll)(bn + grow) * ldb + gc0 * 8;
    const uint32_t sdst = su + grow * PITCH + gc0 * 16;

    // ldmatrix lane offsets (bytes) inside a region
    const uint32_t aOff = (uint32_t)((wm + (lane & 15)) * PITCH + (lane >> 4) * 16);
    const uint32_t bOff = (uint32_t)((wn + (lane & 7) + ((lane >> 4) << 3)) * PITCH
                                     + ((lane >> 3) & 1) * 16);

    float acc[2][8][4] = {};

    auto issue = [&](int cc) {
        const uint32_t d = sdst + (cc & 1) * STAGE_B;
        const int k0 = cc << 5;
        cpa16(d,                  gAh + k0);
        cpa16(d + 16,             gAh + k0 + 8);
        cpa16(d + REGION,         gAl + k0);
        cpa16(d + REGION + 16,    gAl + k0 + 8);
        cpa16(d + 2*REGION,       gBh + k0);
        cpa16(d + 2*REGION + 16,  gBh + k0 + 8);
        cpa16(d + 3*REGION,       gBl + k0);
        cpa16(d + 3*REGION + 16,  gBl + k0 + 8);
    };

    auto compute = [&](int buf) {
        const uint32_t sb = su + buf * STAGE_B;
        const uint32_t aB = sb + aOff;
        const uint32_t bB = sb + 2*REGION + bOff;
        #pragma unroll
        for (int ks = 0; ks < 2; ks++) {
            const uint32_t kb = ks * 32;
            uint32_t ah[2][4], al[2][4];
            ldsm4(ah[0], aB + kb);
            ldsm4(ah[1], aB + 1280 + kb);
            ldsm4(al[0], aB + REGION + kb);
            ldsm4(al[1], aB + REGION + 1280 + kb);
            uint32_t bh0[8], bh1[8], bl0[8], bl1[8];
            #pragma unroll
            for (int p = 0; p < 4; p++) {
                uint32_t t[4];
                ldsm4(t, bB + p * 1280 + kb);
                bh0[2*p] = t[0]; bh1[2*p] = t[1]; bh0[2*p+1] = t[2]; bh1[2*p+1] = t[3];
                ldsm4(t, bB + REGION + p * 1280 + kb);
                bl0[2*p] = t[0]; bl1[2*p] = t[1]; bl0[2*p+1] = t[2]; bl1[2*p+1] = t[3];
            }
            #pragma unroll
            for (int mi = 0; mi < 2; mi++)
                #pragma unroll
                for (int nj = 0; nj < 8; nj++) {
                    mma_bf16(acc[mi][nj], ah[mi], bh0[nj], bh1[nj]);
                    mma_bf16(acc[mi][nj], ah[mi], bl0[nj], bl1[nj]);
                    mma_bf16(acc[mi][nj], al[mi], bh0[nj], bh1[nj]);
                }
        }
    };

    issue(0); cpa_commit();
    if (nc > 1) issue(1);
    cpa_commit();

    for (int cc = 0; cc < nc; cc++) {
        cpa_wait<1>();
        __syncthreads();
        compute(cc & 1);
        __syncthreads();
        if (cc + 2 < nc) issue(cc + 2);
        cpa_commit();
    }

    // Epilogue: frag (g = lane>>2, t = lane&3): rows g,g+8; cols 2t,2t+1
    const int g = lane >> 2, t4 = lane & 3;
    #pragma unroll
    for (int mi = 0; mi < 2; mi++) {
        const int row0 = bm + wm + mi * 16 + g;
        #pragma unroll
        for (int nj = 0; nj < 8; nj++) {
            const int col = bn + wn + nj * 8 + t4 * 2;
            float b0 = 0.f, b1 = 0.f;
            if (biasP) { b0 = biasP[col]; b1 = biasP[col + 1]; }
            float v0x = acc[mi][nj][0] * alpha + b0;
            float v0y = acc[mi][nj][1] * alpha + b1;
            float v1x = acc[mi][nj][2] * alpha + b0;
            float v1y = acc[mi][nj][3] * alpha + b1;
            if (RELU) {
                v0x = fmaxf(v0x, 0.f); v0y = fmaxf(v0y, 0.f);
                v1x = fmaxf(v1x, 0.f); v1y = fmaxf(v1y, 0.f);
            }
            const ll o0 = (ll)row0 * ldc + col;
            const ll o1 = (ll)(row0 + 8) * ldc + col;
            if (EPI == 0) {
                *(float2*)(Cf + o0) = make_float2(v0x, v0y);
                *(float2*)(Cf + o1) = make_float2(v1x, v1y);
            } else {
                hl_store2(Ch, Cl, o0, v0x, v0y);
                hl_store2(Ch, Cl, o1, v1x, v1y);
            }
        }
    }
}

// ---------------------------------------------------------------------------
// Straight fp32 -> hi/lo bf16 convert (no transpose)
// ---------------------------------------------------------------------------
__global__ void convhl_kernel(const float* __restrict__ in,
                              bf16* __restrict__ h, bf16* __restrict__ l, int n4)
{
    int i = blockIdx.x * 256 + threadIdx.x;
    if (i >= n4) return;
    float4 v = ((const float4*)in)[i];
    bf16 hx = __float2bfloat16(v.x), hy = __float2bfloat16(v.y),
         hz = __float2bfloat16(v.z), hw = __float2bfloat16(v.w);
    uint2 hh; hh.x = bpack(hx, hy); hh.y = bpack(hz, hw);
    uint2 llv;
    llv.x = bpack(__float2bfloat16(v.x - __bfloat162float(hx)),
                  __float2bfloat16(v.y - __bfloat162float(hy)));
    llv.y = bpack(__float2bfloat16(v.z - __bfloat162float(hz)),
                  __float2bfloat16(v.w - __bfloat162float(hw)));
    ((uint2*)h)[i] = hh;
    ((uint2*)l)[i] = llv;
}

// ---------------------------------------------------------------------------
// Batched transpose + hi/lo bf16 convert: in fp32 [R,C] -> out bf16 [C,R]
// ---------------------------------------------------------------------------
__global__ void tconv_kernel(const float* __restrict__ in,
                             bf16* __restrict__ hi, bf16* __restrict__ lo,
                             int R, int C, ll zIn, ll zOut)
{
    __shared__ float t[32][33];
    const float* inp = in + (ll)blockIdx.z * zIn;
    bf16* oh = hi + (ll)blockIdx.z * zOut;
    bf16* ol = lo + (ll)blockIdx.z * zOut;
    const int r0 = blockIdx.y * 32, c0 = blockIdx.x * 32;
    const int tx = threadIdx.x, ty = threadIdx.y;
    #pragma unroll
    for (int i = 0; i < 4; i++)
        t[ty + 8 * i][tx] = inp[(ll)(r0 + ty + 8 * i) * C + c0 + tx];
    __syncthreads();
    #pragma unroll
    for (int i = 0; i < 4; i++) {
        int y = ty + 8 * i;
        float v = t[tx][y];
        bf16 h = __float2bfloat16(v);
        ll ofs = (ll)(c0 + y) * R + r0 + tx;
        oh[ofs] = h;
        ol[ofs] = __float2bfloat16(v - __bfloat162float(h));
    }
}

// ---------------------------------------------------------------------------
// Reductions / softmax / layernorm / bias-fold
// ---------------------------------------------------------------------------
__inline__ __device__ float warpRedSum(float v) {
    #pragma unroll
    for (int o = 16; o > 0; o >>= 1) v += __shfl_xor_sync(0xffffffffu, v, o);
    return v;
}
__inline__ __device__ float warpRedMax(float v) {
    #pragma unroll
    for (int o = 16; o > 0; o >>= 1) v = fmaxf(v, __shfl_xor_sync(0xffffffffu, v, o));
    return v;
}

// softmax over fp32 scores -> hi/lo bf16 probabilities
__global__ void softmax_kernel(const float* __restrict__ sc,
                               bf16* __restrict__ oh, bf16* __restrict__ ol,
                               int S, int T, int causal)
{
    const int s = blockIdx.x;
    const ll z = blockIdx.y;
    const ll base = ((ll)z * S + s) * T;
    const float* row = sc + base;
    bf16* rh = oh + base;
    bf16* rl = ol + base;
    const int len = causal ? (s + 1) : T;
    const int tid = threadIdx.x;
    __shared__ float red[8];

    float mx = -1e30f;
    for (int t = tid; t < len; t += 256) mx = fmaxf(mx, row[t]);
    mx = warpRedMax(mx);
    if ((tid & 31) == 0) red[tid >> 5] = mx;
    __syncthreads();
    if (tid == 0) {
        float m = red[0];
        #pragma unroll
        for (int w = 1; w < 8; w++) m = fmaxf(m, red[w]);
        red[0] = m;
    }
    __syncthreads();
    mx = red[0];
    __syncthreads();

    float sum = 0.f;
    for (int t = tid; t < len; t += 256) sum += expf(row[t] - mx);
    sum = warpRedSum(sum);
    if ((tid & 31) == 0) red[tid >> 5] = sum;
    __syncthreads();
    if (tid == 0) {
        float ts = 0.f;
        #pragma unroll
        for (int w = 0; w < 8; w++) ts += red[w];
        red[0] = ts;
    }
    __syncthreads();
    const float inv = 1.0f / red[0];
    for (int t = tid; t < len; t += 256) {
        float v = expf(row[t] - mx) * inv;
        bf16 h = __float2bfloat16(v);
        rh[t] = h;
        rl[t] = __float2bfloat16(v - __bfloat162float(h));
    }
    const bf16 z16 = __float2bfloat16(0.f);
    for (int t = len + tid; t < T; t += 256) { rh[t] = z16; rl[t] = z16; }
}

// out = LayerNorm(a + r) * g + b ; optionally also write hi/lo bf16
__global__ void add_ln_kernel(const float* __restrict__ a, const float* __restrict__ r,
                              const float* __restrict__ g, const float* __restrict__ b,
                              float* __restrict__ out,
                              bf16* __restrict__ oh, bf16* __restrict__ ol)
{
    const ll base = (ll)blockIdx.x * PD;
    const int tid = threadIdx.x;
    __shared__ float red[4];

    float v[4];
    float s = 0.f;
    #pragma unroll
    for (int i = 0; i < 4; i++) {
        int idx = tid + i * 128;
        v[i] = a[base + idx] + r[base + idx];
        s += v[i];
    }
    s = warpRedSum(s);
    if ((tid & 31) == 0) red[tid >> 5] = s;
    __syncthreads();
    const float mean = (red[0] + red[1] + red[2] + red[3]) * (1.f / PD);
    __syncthreads();

    float sq = 0.f;
    #pragma unroll
    for (int i = 0; i < 4; i++) { float d = v[i] - mean; sq += d * d; }
    sq = warpRedSum(sq);
    if ((tid & 31) == 0) red[tid >> 5] = sq;
    __syncthreads();
    const float var = (red[0] + red[1] + red[2] + red[3]) * (1.f / PD);
    const float inv = rsqrtf(var + LN_EPS);

    #pragma unroll
    for (int i = 0; i < 4; i++) {
        int idx = tid + i * 128;
        float o = (v[i] - mean) * inv * g[idx] + b[idx];
        out[base + idx] = o;
        if (oh) {
            bf16 h = __float2bfloat16(o);
            oh[base + idx] = h;
            ol[base + idx] = __float2bfloat16(o - __bfloat162float(h));
        }
    }
}

__global__ void bias_fold_kernel(const float* __restrict__ bo, const float* __restrict__ wf,
                                 const float* __restrict__ bf, float* __restrict__ out)
{
    const int j = blockIdx.x;
    const int tid = threadIdx.x;
    __shared__ float red[8];
    float acc = 0.f;
    for (int k = tid; k < PHD; k += 256) acc += bo[k] * wf[(ll)k * PD + j];
    acc = warpRedSum(acc);
    if ((tid & 31) == 0) red[tid >> 5] = acc;
    __syncthreads();
    if (tid == 0) {
        float t = 0.f;
        #pragma unroll
        for (int w = 0; w < 8; w++) t += red[w];
        out[j] = bf[j] + t;
    }
}

// ---------------------------------------------------------------------------
// Host dispatchers
// ---------------------------------------------------------------------------
static void mmb(const bf16* Ah, const bf16* Al, const bf16* Bh, const bf16* Bl,
                const float* bias, float* Cf, bf16* Ch, bf16* Cl,
                int M, int N, int K, int lda, int ldb, int ldc,
                int Z, int zdiv,
                ll aOut, ll aIn, ll bOut, ll bIn, ll cOut, ll cIn, ll biasIn,
                float alpha, bool relu)
{
    dim3 grid(N / 128, M / 128, Z), block(256);
    if (Cf) {
        mmb_kernel<0, false><<<grid, block, SMEM_DYN>>>(Ah, Al, Bh, Bl, bias, Cf, Ch, Cl,
            K, lda, ldb, ldc, zdiv, aOut, aIn, bOut, bIn, cOut, cIn, biasIn, alpha);
    } else if (relu) {
        mmb_kernel<1, true><<<grid, block, SMEM_DYN>>>(Ah, Al, Bh, Bl, bias, Cf, Ch, Cl,
            K, lda, ldb, ldc, zdiv, aOut, aIn, bOut, bIn, cOut, cIn, biasIn, alpha);
    } else {
        mmb_kernel<1, false><<<grid, block, SMEM_DYN>>>(Ah, Al, Bh, Bl, bias, Cf, Ch, Cl,
            K, lda, ldb, ldc, zdiv, aOut, aIn, bOut, bIn, cOut, cIn, biasIn, alpha);
    }
}

static void tconv(const float* in, bf16* hi, bf16* lo, int R, int C, int Z,
                  ll zIn, ll zOut)
{
    dim3 grid(C / 32, R / 32, Z), block(32, 8);
    tconv_kernel<<<grid, block>>>(in, hi, lo, R, C, zIn, zOut);
}

static void convhl(const float* in, bf16* h, bf16* l, ll n)
{
    int n4 = (int)(n / 4);
    convhl_kernel<<<(n4 + 255) / 256, 256>>>(in, h, l, n4);
}

extern "C" void kernel_launch(void* const* d_in, const int* in_sizes, int n_in,
                              void* d_out, int out_size)
{
    (void)in_sizes; (void)n_in; (void)out_size;
    const float* x      = (const float*)d_in[0];
    const float* enc    = (const float*)d_in[1];
    const float* sa_wq  = (const float*)d_in[2];
    const float* sa_bq  = (const float*)d_in[3];
    const float* sa_wk  = (const float*)d_in[4];
    const float* sa_bk  = (const float*)d_in[5];
    const float* sa_wv  = (const float*)d_in[6];
    const float* sa_bv  = (const float*)d_in[7];
    const float* sa_wo  = (const float*)d_in[8];
    const float* sa_bo  = (const float*)d_in[9];
    const float* sa_wf  = (const float*)d_in[10];
    const float* sa_bf  = (const float*)d_in[11];
    const float* ca_wq  = (const float*)d_in[12];
    const float* ca_bq  = (const float*)d_in[13];
    const float* ca_wk  = (const float*)d_in[14];
    const float* ca_bk  = (const float*)d_in[15];
    const float* ca_wv  = (const float*)d_in[16];
    const float* ca_bv  = (const float*)d_in[17];
    const float* ca_wo  = (const float*)d_in[18];
    const float* ca_bo  = (const float*)d_in[19];
    const float* ca_wf  = (const float*)d_in[20];
    const float* ca_bf  = (const float*)d_in[21];
    const float* ln1_g  = (const float*)d_in[22];
    const float* ln1_b  = (const float*)d_in[23];
    const float* ln2_g  = (const float*)d_in[24];
    const float* ln2_b  = (const float*)d_in[25];
    const float* ln3_g  = (const float*)d_in[26];
    const float* ln3_b  = (const float*)d_in[27];
    const float* fc1_w  = (const float*)d_in[28];
    const float* fc1_b  = (const float*)d_in[29];
    const float* fc2_w  = (const float*)d_in[30];
    const float* fc2_b  = (const float*)d_in[31];

    cudaFuncSetAttribute(mmb_kernel<0, false>, cudaFuncAttributeMaxDynamicSharedMemorySize, SMEM_DYN);
    cudaFuncSetAttribute(mmb_kernel<1, false>, cudaFuncAttributeMaxDynamicSharedMemorySize, SMEM_DYN);
    cudaFuncSetAttribute(mmb_kernel<1, true>,  cudaFuncAttributeMaxDynamicSharedMemorySize, SMEM_DYN);

    float *V, *SC, *ATT, *X1, *X2, *WB, *BT0, *BT1;
    cudaGetSymbolAddress((void**)&V,   g_V);
    cudaGetSymbolAddress((void**)&SC,  g_SC);
    cudaGetSymbolAddress((void**)&ATT, g_ATT);
    cudaGetSymbolAddress((void**)&X1,  g_X1);
    cudaGetSymbolAddress((void**)&X2,  g_X2);
    cudaGetSymbolAddress((void**)&WB,  g_WB);
    cudaGetSymbolAddress((void**)&BT0, g_BT0);
    cudaGetSymbolAddress((void**)&BT1, g_BT1);

    bf16 *xb_h, *xb_l, *encb_h, *encb_l, *wob_h, *wob_l;
    bf16 *Qb_h, *Qb_l, *Kb_h, *Kb_l, *SCb_h, *SCb_l, *CATb_h, *CATb_l;
    bf16 *FFHb_h, *FFHb_l, *X1b_h, *X1b_l, *X2b_h, *X2b_l;
    bf16 *twq_h, *twq_l, *twk_h, *twk_l, *twv_h, *twv_l, *twf_h, *twf_l;
    bf16 *WBT0_h, *WBT0_l, *WBT1_h, *WBT1_l, *tv_h, *tv_l, *tf1_h, *tf1_l, *tf2_h, *tf2_l;
    cudaGetSymbolAddress((void**)&xb_h, g_xb_h);     cudaGetSymbolAddress((void**)&xb_l, g_xb_l);
    cudaGetSymbolAddress((void**)&encb_h, g_encb_h); cudaGetSymbolAddress((void**)&encb_l, g_encb_l);
    cudaGetSymbolAddress((void**)&wob_h, g_wob_h);   cudaGetSymbolAddress((void**)&wob_l, g_wob_l);
    cudaGetSymbolAddress((void**)&Qb_h, g_Qb_h);     cudaGetSymbolAddress((void**)&Qb_l, g_Qb_l);
    cudaGetSymbolAddress((void**)&Kb_h, g_Kb_h);     cudaGetSymbolAddress((void**)&Kb_l, g_Kb_l);
    cudaGetSymbolAddress((void**)&SCb_h, g_SCb_h);   cudaGetSymbolAddress((void**)&SCb_l, g_SCb_l);
    cudaGetSymbolAddress((void**)&CATb_h, g_CATb_h); cudaGetSymbolAddress((void**)&CATb_l, g_CATb_l);
    cudaGetSymbolAddress((void**)&FFHb_h, g_FFHb_h); cudaGetSymbolAddress((void**)&FFHb_l, g_FFHb_l);
    cudaGetSymbolAddress((void**)&X1b_h, g_X1b_h);   cudaGetSymbolAddress((void**)&X1b_l, g_X1b_l);
    cudaGetSymbolAddress((void**)&X2b_h, g_X2b_h);   cudaGetSymbolAddress((void**)&X2b_l, g_X2b_l);
    cudaGetSymbolAddress((void**)&twq_h, g_twq_h);   cudaGetSymbolAddress((void**)&twq_l, g_twq_l);
    cudaGetSymbolAddress((void**)&twk_h, g_twk_h);   cudaGetSymbolAddress((void**)&twk_l, g_twk_l);
    cudaGetSymbolAddress((void**)&twv_h, g_twv_h);   cudaGetSymbolAddress((void**)&twv_l, g_twv_l);
    cudaGetSymbolAddress((void**)&twf_h, g_twf_h);   cudaGetSymbolAddress((void**)&twf_l, g_twf_l);
    cudaGetSymbolAddress((void**)&WBT0_h, g_WBT0_h); cudaGetSymbolAddress((void**)&WBT0_l, g_WBT0_l);
    cudaGetSymbolAddress((void**)&WBT1_h, g_WBT1_h); cudaGetSymbolAddress((void**)&WBT1_l, g_WBT1_l);
    cudaGetSymbolAddress((void**)&tv_h, g_tv_h);     cudaGetSymbolAddress((void**)&tv_l, g_tv_l);
    cudaGetSymbolAddress((void**)&tf1_h, g_tf1_h);   cudaGetSymbolAddress((void**)&tf1_l, g_tf1_l);
    cudaGetSymbolAddress((void**)&tf2_h, g_tf2_h);   cudaGetSymbolAddress((void**)&tf2_l, g_tf2_l);

    const float inv_sqrt_d = 0.04419417382415922f;   // 1/sqrt(512)

    // ---- one-shot input conversions ----
    convhl(x, xb_h, xb_l, (ll)PBS * PD);
    convhl(enc, encb_h, encb_l, (ll)PBS * PD);

    // ---- Fold wo@wf -> WBT, bo@wf+bf -> bias_tot (both attentions) ----
    convhl(sa_wo, wob_h, wob_l, (ll)PH * DDc);
    tconv(sa_wf, twf_h, twf_l, PHD, PD, 1, 0, 0);
    mmb(wob_h, wob_l, twf_h, twf_l, nullptr, WB, nullptr, nullptr,
        PD, PD, PD, PD, PHD, PD, PH, PH,
        0, DDc, 0, 512, 0, DDc, 0, 1.f, false);
    bias_fold_kernel<<<PD, 256>>>(sa_bo, sa_wf, sa_bf, BT0);
    tconv(WB, WBT0_h, WBT0_l, PHD, PD, 1, 0, 0);

    convhl(ca_wo, wob_h, wob_l, (ll)PH * DDc);
    tconv(ca_wf, twf_h, twf_l, PHD, PD, 1, 0, 0);
    mmb(wob_h, wob_l, twf_h, twf_l, nullptr, WB, nullptr, nullptr,
        PD, PD, PD, PD, PHD, PD, PH, PH,
        0, DDc, 0, 512, 0, DDc, 0, 1.f, false);
    bias_fold_kernel<<<PD, 256>>>(ca_bo, ca_wf, ca_bf, BT1);
    tconv(WB, WBT1_h, WBT1_l, PHD, PD, 1, 0, 0);

    // ======================= Self-attention =======================
    tconv(sa_wq, twq_h, twq_l, PD, PD, PH, DDc, DDc);
    tconv(sa_wk, twk_h, twk_l, PD, PD, PH, DDc, DDc);
    tconv(sa_wv, twv_h, twv_l, PD, PD, PH, DDc, DDc);
    // projections (z = b*8+h): Q,K -> hi/lo only; V -> fp32
    mmb(xb_h, xb_l, twq_h, twq_l, sa_bq, nullptr, Qb_h, Qb_l,
        PS, PD, PD, PD, PD, PD, PB * PH, PH,
        SDc, 0, 0, DDc, (ll)PH * SDc, SDc, PD, 1.f, false);
    mmb(xb_h, xb_l, twk_h, twk_l, sa_bk, nullptr, Kb_h, Kb_l,
        PS, PD, PD, PD, PD, PD, PB * PH, PH,
        SDc, 0, 0, DDc, (ll)PH * SDc, SDc, PD, 1.f, false);
    mmb(xb_h, xb_l, twv_h, twv_l, sa_bv, V, nullptr, nullptr,
        PS, PD, PD, PD, PD, PD, PB * PH, PH,
        SDc, 0, 0, DDc, (ll)PH * SDc, SDc, PD, 1.f, false);
    // scores = Q @ K^T / sqrt(D) -> fp32
    mmb(Qb_h, Qb_l, Kb_h, Kb_l, nullptr, SC, nullptr, nullptr,
        PS, PT, PD, PD, PD, PT, PB * PH, PB * PH,
        0, SDc, 0, SDc, 0, STc, 0, inv_sqrt_d, false);
    softmax_kernel<<<dim3(PS, PB * PH), 256>>>(SC, SCb_h, SCb_l, PS, PT, 1);
    tconv(V, tv_h, tv_l, PT, PD, PB * PH, SDc, SDc);
    // AV -> CAT hi/lo [B,S,H*D]
    mmb(SCb_h, SCb_l, tv_h, tv_l, nullptr, nullptr, CATb_h, CATb_l,
        PS, PD, PT, PT, PT, PHD, PB * PH, PH,
        (ll)PH * STc, STc, (ll)PH * SDc, SDc, (ll)PS * PHD, PD, 0, 1.f, false);
    // attn = CAT @ WB + bias_tot -> fp32
    mmb(CATb_h, CATb_l, WBT0_h, WBT0_l, BT0, ATT, nullptr, nullptr,
        PBS, PD, PHD, PHD, PHD, PD, 1, 1,
        0, 0, 0, 0, 0, 0, 0, 1.f, false);
    add_ln_kernel<<<PBS, 128>>>(ATT, x, ln1_g, ln1_b, X1, X1b_h, X1b_l);

    // ======================= Cross-attention =======================
    tconv(ca_wq, twq_h, twq_l, PD, PD, PH, DDc, DDc);
    tconv(ca_wk, twk_h, twk_l, PD, PD, PH, DDc, DDc);
    tconv(ca_wv, twv_h, twv_l, PD, PD, PH, DDc, DDc);
    mmb(X1b_h, X1b_l, twq_h, twq_l, ca_bq, nullptr, Qb_h, Qb_l,
        PS, PD, PD, PD, PD, PD, PB * PH, PH,
        SDc, 0, 0, DDc, (ll)PH * SDc, SDc, PD, 1.f, false);
    mmb(encb_h, encb_l, twk_h, twk_l, ca_bk, nullptr, Kb_h, Kb_l,
        PT, PD, PD, PD, PD, PD, PB * PH, PH,
        (ll)PT * PD, 0, 0, DDc, (ll)PH * SDc, SDc, PD, 1.f, false);
    mmb(encb_h, encb_l, twv_h, twv_l, ca_bv, V, nullptr, nullptr,
        PT, PD, PD, PD, PD, PD, PB * PH, PH,
        (ll)PT * PD, 0, 0, DDc, (ll)PH * SDc, SDc, PD, 1.f, false);
    mmb(Qb_h, Qb_l, Kb_h, Kb_l, nullptr, SC, nullptr, nullptr,
        PS, PT, PD, PD, PD, PT, PB * PH, PB * PH,
        0, SDc, 0, SDc, 0, STc, 0, inv_sqrt_d, false);
    softmax_kernel<<<dim3(PS, PB * PH), 256>>>(SC, SCb_h, SCb_l, PS, PT, 0);
    tconv(V, tv_h, tv_l, PT, PD, PB * PH, SDc, SDc);
    mmb(SCb_h, SCb_l, tv_h, tv_l, nullptr, nullptr, CATb_h, CATb_l,
        PS, PD, PT, PT, PT, PHD, PB * PH, PH,
        (ll)PH * STc, STc, (ll)PH * SDc, SDc, (ll)PS * PHD, PD, 0, 1.f, false);
    mmb(CATb_h, CATb_l, WBT1_h, WBT1_l, BT1, ATT, nullptr, nullptr,
        PBS, PD, PHD, PHD, PHD, PD, 1, 1,
        0, 0, 0, 0, 0, 0, 0, 1.f, false);
    add_ln_kernel<<<PBS, 128>>>(ATT, X1, ln2_g, ln2_b, X2, X2b_h, X2b_l);

    // ======================= FFN =======================
    tconv(fc1_w, tf1_h, tf1_l, PD, 4 * PD, 1, 0, 0);                  // [2048,512]
    mmb(X2b_h, X2b_l, tf1_h, tf1_l, fc1_b, nullptr, FFHb_h, FFHb_l,
        PBS, 4 * PD, PD, PD, PD, 4 * PD, 1, 1,
        0, 0, 0, 0, 0, 0, 0, 1.f, true);
    tconv(fc2_w, tf2_h, tf2_l, 4 * PD, PD, 1, 0, 0);                  // [512,2048]
    mmb(FFHb_h, FFHb_l, tf2_h, tf2_l, fc2_b, ATT, nullptr, nullptr,
        PBS, PD, 4 * PD, 4 * PD, 4 * PD, PD, 1, 1,
        0, 0, 0, 0, 0, 0, 0, 1.f, false);
    add_ln_kernel<<<PBS, 128>>>(ATT, X2, ln3_g, ln3_b, (float*)d_out, nullptr, nullptr);
}